// round 6
// baseline (speedup 1.0000x reference)
#include <cuda_runtime.h>
#include <stdint.h>

#define BB 4
#define NN 4096
#define DD 128
#define KK 2048
#define EPSV 1e-10f
#define RPB 4     // rows per gatherg block

// ---- scratch (no allocation allowed) ----
__device__ unsigned long long d_keys[BB * NN];   // 128 KB
__device__ int   d_idx[BB * KK];
__device__ float d_vals[BB * KK];
__device__ int   d_arrive[BB];                   // per-batch barrier counters

// output layout: g_new | new_h | idx (float32)
#define OFF_G 0
#define OFF_H ((size_t)BB * KK * KK)
#define OFF_I (OFF_H + (size_t)BB * KK * DD)

__device__ __forceinline__ unsigned smem_u32(const void* p) {
    unsigned a;
    asm("{ .reg .u64 t; cvta.to.shared.u64 t, %1; cvt.u32.u64 %0, t; }" : "=r"(a) : "l"(p));
    return a;
}

// ---------------------------------------------------------------------------
// Kernel 1 (fused): scores + exact rank-by-count.
// 128 blocks (32/batch) x 256 threads; all blocks resident in wave 1 (<148
// SMs), so a per-batch atomic spin barrier is deadlock-free.
// Phase A: each block computes scores for its 128 nodes -> global keys.
// Barrier: release-arrive / acquire-spin on d_arrive[b].
// Phase B: load all 4096 batch keys to smem, rank own 128 nodes (compare
// range split across thread pairs), scatter idx/vals in score order.
// key = (sigmoid_bits << 32) | (0xFFFFFFFF - node): descending key order ==
// descending score with ascending-index ties (jax.lax.top_k semantics).
// ---------------------------------------------------------------------------
__global__ void __launch_bounds__(256) select_kernel(const float4* __restrict__ h,
                                                     const float4* __restrict__ w,
                                                     const float* __restrict__ bptr) {
    __shared__ __align__(16) unsigned long long sk[NN];   // 32 KB
    __shared__ int part[128];
    const int b   = blockIdx.x >> 5;
    const int blk = blockIdx.x & 31;
    const int tid = threadIdx.x;
    const int wid = tid >> 5, lane = tid & 31;

    // ---- Phase A: scores for nodes blk*128 .. +127 (16 per warp) ----
    const float bias = bptr[0];
    const float4 wv = w[lane];
    #pragma unroll
    for (int pass = 0; pass < 4; pass++) {
        const int n0 = blk * 128 + wid * 16 + pass * 4;   // 4 nodes this pass
        float s[4];
        #pragma unroll
        for (int u = 0; u < 4; u++) {
            float4 a = h[((size_t)b * NN + n0 + u) * (DD / 4) + lane];
            s[u] = a.x * wv.x + a.y * wv.y + a.z * wv.z + a.w * wv.w;
        }
        #pragma unroll
        for (int o = 16; o; o >>= 1) {
            #pragma unroll
            for (int u = 0; u < 4; u++) s[u] += __shfl_xor_sync(0xFFFFFFFFu, s[u], o);
        }
        if (lane < 4) {
            int nd = n0 + lane;
            float sc = 1.0f / (1.0f + expf(-(s[lane] + bias)));
            unsigned sb = __float_as_uint(sc);
            d_keys[b * NN + nd] = ((unsigned long long)sb << 32) |
                                  (unsigned long long)(0xFFFFFFFFu - (unsigned)nd);
        }
    }
    __syncthreads();

    // ---- per-batch barrier: release my keys, acquire everyone's ----
    if (tid == 0) {
        __threadfence();                                   // release
        atomicAdd(&d_arrive[b], 1);
        int seen;
        do {
            asm volatile("ld.acquire.gpu.global.s32 %0, [%1];"
                         : "=r"(seen) : "l"(&d_arrive[b]) : "memory");
        } while (seen < 32);
    }
    __syncthreads();

    // ---- Phase B: rank ----
    for (int i = tid; i < NN; i += 256) sk[i] = d_keys[b * NN + i];
    __syncthreads();

    const int node = blk * 128 + (tid & 127);
    const int half = tid >> 7;
    const unsigned long long my = sk[node];
    const ulonglong2* sk2 = (const ulonglong2*)(sk + half * (NN / 2));
    int r = 0;
    #pragma unroll 8
    for (int i = 0; i < NN / 4; i++) {
        ulonglong2 kk = sk2[i];
        r += (kk.x > my) + (kk.y > my);
    }
    if (half) part[tid & 127] = r;
    __syncthreads();
    if (!half) {
        r += part[tid];
        if (r < KK) {
            d_idx [b * KK + r] = node;
            d_vals[b * KK + r] = __uint_as_float((unsigned int)(my >> 32));
        }
    }
}

// ---------------------------------------------------------------------------
// Kernel 2: gathered adjacency + degree normalize, fused new_h + idx.
// Per-thread cp.async staging, 2-buffer lookahead via cp.async.wait_group.
// All global stores use .cs (streaming) — nothing written is ever re-read.
// ---------------------------------------------------------------------------
__global__ void __launch_bounds__(256) gatherg_kernel(const float* __restrict__ g,
                                                      const float* __restrict__ h,
                                                      float* __restrict__ out) {
    __shared__ __align__(16) float buf[2][NN];              // 32 KB
    __shared__ float wsum[8];

    const int b    = blockIdx.y;
    const int base = blockIdx.x * RPB;
    const int tid  = threadIdx.x;

    auto issue_row = [&](int r, int st) {
        const int node = __ldg(d_idx + b * KK + base + r);
        const char* gsrc = (const char*)(g + ((size_t)b * NN + node) * NN) + tid * 16;
        unsigned sdst = smem_u32(buf[st]) + tid * 16;
        #pragma unroll
        for (int c = 0; c < 4; c++) {
            asm volatile("cp.async.cg.shared.global [%0], [%1], 16;"
                         :: "r"(sdst + c * 4096), "l"(gsrc + c * 4096) : "memory");
        }
        asm volatile("cp.async.commit_group;" ::: "memory");
    };

    issue_row(0, 0);
    issue_row(1, 1);

    const int4* cp4 = (const int4*)(d_idx + b * KK);
    const int4 c0 = cp4[tid * 2];
    const int4 c1 = cp4[tid * 2 + 1];

    #pragma unroll
    for (int r = 0; r < RPB; r++) {
        const int   st   = r & 1;
        const int   row  = b * KK + base + r;
        const int   node = d_idx[row];
        const float v    = d_vals[row];

        // fused new_h + idx (independent of buf; overlaps pending copies)
        if (tid < 32) {
            float4 hv = __ldg((const float4*)(h + ((size_t)b * NN + node) * DD) + tid);
            hv.x *= v; hv.y *= v; hv.z *= v; hv.w *= v;
            __stcs((float4*)(out + OFF_H + (size_t)row * DD) + tid, hv);
        }
        if (tid == 32) __stcs(out + OFF_I + row, (float)node);

        if (r < RPB - 1)
            asm volatile("cp.async.wait_group 1;" ::: "memory");
        else
            asm volatile("cp.async.wait_group 0;" ::: "memory");
        __syncthreads();

        const float* srow = buf[st];
        float vv[8];
        vv[0] = srow[c0.x]; vv[1] = srow[c0.y]; vv[2] = srow[c0.z]; vv[3] = srow[c0.w];
        vv[4] = srow[c1.x]; vv[5] = srow[c1.y]; vv[6] = srow[c1.z]; vv[7] = srow[c1.w];
        float local = (vv[0] + vv[1]) + (vv[2] + vv[3]) +
                      ((vv[4] + vv[5]) + (vv[6] + vv[7]));
        #pragma unroll
        for (int o = 16; o; o >>= 1) local += __shfl_xor_sync(0xFFFFFFFFu, local, o);
        if ((tid & 31) == 0) wsum[tid >> 5] = local;
        __syncthreads();

        float deg = 0.f;
        #pragma unroll
        for (int wv = 0; wv < 8; wv++) deg += wsum[wv];
        const float inv = 1.0f / (deg + EPSV);

        if (r + 2 < RPB) issue_row(r + 2, st);   // next fetch before the writes

        float4* dst4 = (float4*)(out + OFF_G + (size_t)row * KK);
        __stcs(dst4 + tid * 2,
               make_float4(vv[0] * inv, vv[1] * inv, vv[2] * inv, vv[3] * inv));
        __stcs(dst4 + tid * 2 + 1,
               make_float4(vv[4] * inv, vv[5] * inv, vv[6] * inv, vv[7] * inv));
    }
}

// ---------------------------------------------------------------------------
extern "C" void kernel_launch(void* const* d_in, const int* in_sizes, int n_in,
                              void* d_out, int out_size) {
    const float* g = (const float*)d_in[0];   // [B,N,N]
    const float* h = (const float*)d_in[1];   // [B,N,D]
    const float* w = (const float*)d_in[2];   // [D]
    const float* b = (const float*)d_in[3];   // scalar
    float* out = (float*)d_out;

    int* arrive_ptr = nullptr;
    cudaGetSymbolAddress((void**)&arrive_ptr, d_arrive);
    cudaMemsetAsync(arrive_ptr, 0, BB * sizeof(int));

    select_kernel<<<BB * 32, 256>>>((const float4*)h, (const float4*)w, b);
    dim3 grid(KK / RPB, BB);
    gatherg_kernel<<<grid, 256>>>(g, h, out);
}

// round 7
// speedup vs baseline: 1.1885x; 1.1885x over previous
#include <cuda_runtime.h>
#include <stdint.h>

#define BB 4
#define NN 4096
#define DD 128
#define KK 2048
#define EPSV 1e-10f
#define RPB 4     // rows per gatherg block

// ---- scratch (no allocation allowed) ----
__device__ unsigned long long d_keys[BB * NN];   // 128 KB
__device__ int   d_idx[BB * KK];
__device__ float d_vals[BB * KK];

// output layout: g_new | new_h | idx (float32)
#define OFF_G 0
#define OFF_H ((size_t)BB * KK * KK)
#define OFF_I (OFF_H + (size_t)BB * KK * DD)

__device__ __forceinline__ unsigned smem_u32(const void* p) {
    unsigned a;
    asm("{ .reg .u64 t; cvta.to.shared.u64 t, %1; cvt.u32.u64 %0, t; }" : "=r"(a) : "l"(p));
    return a;
}

// ---------------------------------------------------------------------------
// Kernel 1: scores = sigmoid(h . w + b) packed into sortable u64 keys.
// key = (score_bits << 32) | (0xFFFFFFFF - node): descending key order ==
// descending score, ascending node on ties (jax.lax.top_k). 4 nodes/warp.
// ---------------------------------------------------------------------------
__global__ void scores_kernel(const float4* __restrict__ h,
                              const float4* __restrict__ w,
                              const float* __restrict__ bptr) {
    int gwarp = (blockIdx.x * blockDim.x + threadIdx.x) >> 5;
    int lane  = threadIdx.x & 31;
    int n0 = gwarp * 4;
    if (n0 >= BB * NN) return;
    float4 wv = w[lane];
    float s[4];
    #pragma unroll
    for (int u = 0; u < 4; u++) {
        float4 a = h[(size_t)(n0 + u) * (DD / 4) + lane];
        s[u] = a.x * wv.x + a.y * wv.y + a.z * wv.z + a.w * wv.w;
    }
    #pragma unroll
    for (int o = 16; o; o >>= 1) {
        #pragma unroll
        for (int u = 0; u < 4; u++) s[u] += __shfl_xor_sync(0xFFFFFFFFu, s[u], o);
    }
    if (lane < 4) {
        int nd = n0 + lane;
        float x  = s[lane] + bptr[0];
        float sc = 1.0f / (1.0f + expf(-x));
        unsigned int sb = __float_as_uint(sc);
        unsigned int node = (unsigned int)(nd & (NN - 1));
        d_keys[nd] = ((unsigned long long)sb << 32) |
                     (unsigned long long)(0xFFFFFFFFu - node);
    }
}

// ---------------------------------------------------------------------------
// Kernel 2: exact rank-by-count (keys unique). 512 threads / 128 nodes per
// block: each node's 4096 compares split across FOUR threads (1024 keys
// each), partials combined in smem. 32 blocks per batch.
// ---------------------------------------------------------------------------
__global__ void __launch_bounds__(512) rank_kernel() {
    __shared__ __align__(16) unsigned long long sk[NN];   // 32 KB
    __shared__ int part[3][128];
    const int b   = blockIdx.x >> 5;
    const int blk = blockIdx.x & 31;
    const int tid = threadIdx.x;           // 512 threads
    for (int i = tid; i < NN; i += 512) sk[i] = d_keys[b * NN + i];
    __syncthreads();

    const int node = blk * 128 + (tid & 127);
    const int q    = tid >> 7;             // quarter 0..3
    const unsigned long long my = sk[node];
    const ulonglong2* sk2 = (const ulonglong2*)(sk + q * (NN / 4));
    int r = 0;
    #pragma unroll 8
    for (int i = 0; i < NN / 8; i++) {
        ulonglong2 kk = sk2[i];
        r += (kk.x > my) + (kk.y > my);
    }
    if (q) part[q - 1][tid & 127] = r;
    __syncthreads();
    if (!q) {
        r += part[0][tid] + part[1][tid] + part[2][tid];
        if (r < KK) {
            d_idx [b * KK + r] = node;
            d_vals[b * KK + r] = __uint_as_float((unsigned int)(my >> 32));
        }
    }
}

// ---------------------------------------------------------------------------
// Kernel 3: gathered adjacency + degree normalize, fused new_h + idx.
// Per-thread cp.async staging, 2-buffer lookahead via cp.async.wait_group.
// Next row's copy is issued BEFORE the current row's output stores.
// (Exact R5 structure — measured fastest.)
// ---------------------------------------------------------------------------
__global__ void __launch_bounds__(256) gatherg_kernel(const float* __restrict__ g,
                                                      const float* __restrict__ h,
                                                      float* __restrict__ out) {
    __shared__ __align__(16) float buf[2][NN];              // 32 KB
    __shared__ float wsum[8];

    const int b    = blockIdx.y;
    const int base = blockIdx.x * RPB;
    const int tid  = threadIdx.x;

    auto issue_row = [&](int r, int st) {
        const int node = d_idx[b * KK + base + r];
        const char* gsrc = (const char*)(g + ((size_t)b * NN + node) * NN) + tid * 16;
        unsigned sdst = smem_u32(buf[st]) + tid * 16;
        #pragma unroll
        for (int c = 0; c < 4; c++) {
            asm volatile("cp.async.cg.shared.global [%0], [%1], 16;"
                         :: "r"(sdst + c * 4096), "l"(gsrc + c * 4096) : "memory");
        }
        asm volatile("cp.async.commit_group;" ::: "memory");
    };

    issue_row(0, 0);
    issue_row(1, 1);

    const int4* cp4 = (const int4*)(d_idx + b * KK);
    const int4 c0 = cp4[tid * 2];
    const int4 c1 = cp4[tid * 2 + 1];

    #pragma unroll
    for (int r = 0; r < RPB; r++) {
        const int   st   = r & 1;
        const int   row  = b * KK + base + r;
        const int   node = d_idx[row];
        const float v    = d_vals[row];

        // fused new_h + idx (independent of buf; overlaps pending copies)
        if (tid < 32) {
            float4 hv = __ldg((const float4*)(h + ((size_t)b * NN + node) * DD) + tid);
            hv.x *= v; hv.y *= v; hv.z *= v; hv.w *= v;
            ((float4*)(out + OFF_H + (size_t)row * DD))[tid] = hv;
        }
        if (tid == 32) out[OFF_I + row] = (float)node;

        if (r < RPB - 1)
            asm volatile("cp.async.wait_group 1;" ::: "memory");
        else
            asm volatile("cp.async.wait_group 0;" ::: "memory");
        __syncthreads();

        const float* srow = buf[st];
        float vv[8];
        vv[0] = srow[c0.x]; vv[1] = srow[c0.y]; vv[2] = srow[c0.z]; vv[3] = srow[c0.w];
        vv[4] = srow[c1.x]; vv[5] = srow[c1.y]; vv[6] = srow[c1.z]; vv[7] = srow[c1.w];
        float local = (vv[0] + vv[1]) + (vv[2] + vv[3]) +
                      ((vv[4] + vv[5]) + (vv[6] + vv[7]));
        #pragma unroll
        for (int o = 16; o; o >>= 1) local += __shfl_xor_sync(0xFFFFFFFFu, local, o);
        if ((tid & 31) == 0) wsum[tid >> 5] = local;
        __syncthreads();

        float deg = 0.f;
        #pragma unroll
        for (int wv = 0; wv < 8; wv++) deg += wsum[wv];
        const float inv = 1.0f / (deg + EPSV);

        if (r + 2 < RPB) issue_row(r + 2, st);   // next fetch before the writes

        float4* dst4 = (float4*)(out + OFF_G + (size_t)row * KK);
        dst4[tid * 2]     = make_float4(vv[0] * inv, vv[1] * inv, vv[2] * inv, vv[3] * inv);
        dst4[tid * 2 + 1] = make_float4(vv[4] * inv, vv[5] * inv, vv[6] * inv, vv[7] * inv);
    }
}

// ---------------------------------------------------------------------------
extern "C" void kernel_launch(void* const* d_in, const int* in_sizes, int n_in,
                              void* d_out, int out_size) {
    const float* g = (const float*)d_in[0];   // [B,N,N]
    const float* h = (const float*)d_in[1];   // [B,N,D]
    const float* w = (const float*)d_in[2];   // [D]
    const float* b = (const float*)d_in[3];   // scalar
    float* out = (float*)d_out;

    scores_kernel<<<(BB * NN) / 16, 128>>>((const float4*)h, (const float4*)w, b);
    rank_kernel<<<BB * 32, 512>>>();
    dim3 grid(KK / RPB, BB);
    gatherg_kernel<<<grid, 256>>>(g, h, out);
}